// round 1
// baseline (speedup 1.0000x reference)
#include <cuda_runtime.h>
#include <math.h>

#define S_LEN 2048
#define HID   1024
#define NH    16
#define HD    64
#define BATCH 2
#define ROWS  (BATCH * S_LEN)   // 4096

// -------- scratch (static __device__ arrays; no allocation allowed) --------
__device__ float g_qkv[(size_t)ROWS * 3 * HID];  // [4096][3072]  (3, nh, hd) per row
__device__ float g_att[(size_t)ROWS * HID];      // attention output, [B*S][H]
__device__ float g_cos[S_LEN * 32];
__device__ float g_sin[S_LEN * 32];

// =============================== SGEMM =====================================
// C[M,N] = A[M,K] * B[K,N], row-major, M%128==0, N%128==0, K%16==0
#define BM 128
#define BN 128
#define BK 16

__global__ __launch_bounds__(256) void sgemm_kernel(
    const float* __restrict__ A, const float* __restrict__ B,
    float* __restrict__ C, int M, int N, int K)
{
    __shared__ float As[BK][BM + 1];   // +1 pad: conflict-free transposed stores/reads
    __shared__ float Bs[BK][BN];

    const int tid = threadIdx.x;
    const int tx = tid & 15, ty = tid >> 4;
    const int m0 = blockIdx.y * BM, n0 = blockIdx.x * BN;

    float acc[8][8];
#pragma unroll
    for (int r = 0; r < 8; r++)
#pragma unroll
        for (int c = 0; c < 8; c++) acc[r][c] = 0.f;

    for (int k0 = 0; k0 < K; k0 += BK) {
        // A tile: 128x16 = 512 float4, 2 per thread, stored transposed
#pragma unroll
        for (int i = 0; i < 2; i++) {
            int f = tid + 256 * i;
            int r = f >> 2, c4 = (f & 3) << 2;
            const float4 v = *(const float4*)(A + (size_t)(m0 + r) * K + k0 + c4);
            As[c4 + 0][r] = v.x; As[c4 + 1][r] = v.y;
            As[c4 + 2][r] = v.z; As[c4 + 3][r] = v.w;
        }
        // B tile: 16x128 = 512 float4, 2 per thread
#pragma unroll
        for (int i = 0; i < 2; i++) {
            int f = tid + 256 * i;
            int r = f >> 5, c4 = (f & 31) << 2;
            *(float4*)(&Bs[r][c4]) = *(const float4*)(B + (size_t)(k0 + r) * N + n0 + c4);
        }
        __syncthreads();

#pragma unroll
        for (int kk = 0; kk < BK; kk++) {
            float a[8], b[8];
#pragma unroll
            for (int i = 0; i < 8; i++) a[i] = As[kk][ty * 8 + i];
#pragma unroll
            for (int i = 0; i < 8; i += 4)
                *(float4*)&b[i] = *(const float4*)&Bs[kk][tx * 8 + i];
#pragma unroll
            for (int r = 0; r < 8; r++)
#pragma unroll
                for (int c = 0; c < 8; c++) acc[r][c] += a[r] * b[c];
        }
        __syncthreads();
    }

#pragma unroll
    for (int r = 0; r < 8; r++) {
        float* crow = C + (size_t)(m0 + ty * 8 + r) * N + n0 + tx * 8;
#pragma unroll
        for (int c = 0; c < 8; c += 4) {
            float4 v = make_float4(acc[r][c], acc[r][c + 1], acc[r][c + 2], acc[r][c + 3]);
            *(float4*)(crow + c) = v;
        }
    }
}

// ============================ RoPE tables ==================================
__global__ void rope_tables_kernel()
{
    int idx = blockIdx.x * blockDim.x + threadIdx.x;
    if (idx >= S_LEN * 32) return;
    int s = idx >> 5, j = idx & 31;
    double inv = exp(-((double)j / 32.0) * log(160000.0));
    double ang = (double)s * inv;
    g_cos[idx] = (float)cos(ang);
    g_sin[idx] = (float)sin(ang);
}

// ======================= RoPE apply (in-place on qkv) ======================
// thread handles one (row, tensor(q|k), head, pair j): both halves of the pair
__global__ __launch_bounds__(256) void rope_apply_kernel()
{
    int idx = blockIdx.x * blockDim.x + threadIdx.x;   // 4096*1024 threads
    if (idx >= ROWS * 1024) return;
    int row  = idx >> 10;
    int rem  = idx & 1023;
    int t    = rem >> 9;          // 0 = q, 1 = k
    int rem2 = rem & 511;
    int h    = rem2 >> 5;
    int j    = rem2 & 31;
    int s    = row & (S_LEN - 1);

    size_t base = (size_t)row * 3072 + (size_t)t * HID + h * HD;
    float x1 = g_qkv[base + j];
    float x2 = g_qkv[base + j + 32];
    float c  = g_cos[s * 32 + j];
    float sn = g_sin[s * 32 + j];
    g_qkv[base + j]      = x1 * c - x2 * sn;
    g_qkv[base + j + 32] = x2 * c + x1 * sn;
}

// ======================= fused causal flash attention ======================
// block: (qtile, b*nh). 256 threads. 64x64 tiles, online softmax.
// thread t: row i = t>>2, owns j/c lanes {g, g+4, ..., g+60} with g = t&3.
__global__ __launch_bounds__(256) void attn_kernel(
    const float* __restrict__ qkv, float* __restrict__ out)
{
    extern __shared__ float sm[];
    float* Qs   = sm;            // 64*65
    float* Ks   = sm + 4160;     // 64*65
    float* Vs   = sm + 8320;     // 64*65
    float* Ss   = sm + 12480;    // 64*65
    float* m_sh = sm + 16640;    // 64
    float* l_sh = sm + 16704;    // 64  (total 16768 floats = 67072 B)

    const int tid = threadIdx.x;
    const int qt = blockIdx.x, bh = blockIdx.y;
    const int b = bh >> 4, h = bh & 15;
    const int q0 = qt * 64;
    const size_t rowbase = (size_t)b * S_LEN;
    const int qoff = h * HD, koff = HID + h * HD, voff = 2 * HID + h * HD;

    const int i = tid >> 2, g = tid & 3;

    // load Q tile (64 x 64)
    for (int f = tid; f < 1024; f += 256) {
        int r = f >> 4, c4 = (f & 15) << 2;
        float4 v = *(const float4*)(qkv + (rowbase + q0 + r) * 3072 + qoff + c4);
        Qs[r * 65 + c4 + 0] = v.x; Qs[r * 65 + c4 + 1] = v.y;
        Qs[r * 65 + c4 + 2] = v.z; Qs[r * 65 + c4 + 3] = v.w;
    }
    if (tid < 64) { m_sh[tid] = -INFINITY; l_sh[tid] = 0.f; }

    float O[16];
#pragma unroll
    for (int c = 0; c < 16; c++) O[c] = 0.f;

    for (int j0 = 0; j0 <= q0; j0 += 64) {
        __syncthreads();   // prev PV done with Vs/Ss
        for (int f = tid; f < 1024; f += 256) {
            int r = f >> 4, c4 = (f & 15) << 2;
            const float* rowp = qkv + (rowbase + j0 + r) * 3072;
            float4 kv = *(const float4*)(rowp + koff + c4);
            Ks[r * 65 + c4 + 0] = kv.x; Ks[r * 65 + c4 + 1] = kv.y;
            Ks[r * 65 + c4 + 2] = kv.z; Ks[r * 65 + c4 + 3] = kv.w;
            float4 vv = *(const float4*)(rowp + voff + c4);
            Vs[r * 65 + c4 + 0] = vv.x; Vs[r * 65 + c4 + 1] = vv.y;
            Vs[r * 65 + c4 + 2] = vv.z; Vs[r * 65 + c4 + 3] = vv.w;
        }
        float m_prev = m_sh[i];
        __syncthreads();   // K/V tiles ready

        // S = Q K^T for my 16 strided j's
        float s[16];
#pragma unroll
        for (int jj = 0; jj < 16; jj++) s[jj] = 0.f;
        for (int d = 0; d < 64; d++) {
            float qv = Qs[i * 65 + d];
#pragma unroll
            for (int jj = 0; jj < 16; jj++)
                s[jj] += qv * Ks[(g + (jj << 2)) * 65 + d];
        }

        const bool diag = (j0 == q0);
        float mloc = -INFINITY;
#pragma unroll
        for (int jj = 0; jj < 16; jj++) {
            float val = s[jj] * 0.125f;
            if (diag && (g + (jj << 2)) > i) val = -1e9f;
            s[jj] = val;
            mloc = fmaxf(mloc, val);
        }
        mloc = fmaxf(mloc, __shfl_xor_sync(0xffffffffu, mloc, 1));
        mloc = fmaxf(mloc, __shfl_xor_sync(0xffffffffu, mloc, 2));
        float m_new = fmaxf(m_prev, mloc);

        float ssum = 0.f;
#pragma unroll
        for (int jj = 0; jj < 16; jj++) {
            float p = expf(s[jj] - m_new);
            ssum += p;
            Ss[i * 65 + g + (jj << 2)] = p;
        }
        ssum += __shfl_xor_sync(0xffffffffu, ssum, 1);
        ssum += __shfl_xor_sync(0xffffffffu, ssum, 2);
        float alpha = expf(m_prev - m_new);
        if (g == 0) { m_sh[i] = m_new; l_sh[i] = l_sh[i] * alpha + ssum; }
        __syncthreads();   // Ss ready

        // O = O*alpha + P @ V  (my row i, 16 strided columns)
#pragma unroll
        for (int c = 0; c < 16; c++) O[c] *= alpha;
        for (int j = 0; j < 64; j++) {
            float pv = Ss[i * 65 + j];
#pragma unroll
            for (int c = 0; c < 16; c++)
                O[c] += pv * Vs[j * 65 + g + (c << 2)];
        }
    }

    __syncthreads();
    float linv = 1.0f / l_sh[i];
#pragma unroll
    for (int c = 0; c < 16; c++)
        out[(rowbase + q0 + i) * HID + h * HD + g + (c << 2)] = O[c] * linv;
}

// ================================ launch ===================================
extern "C" void kernel_launch(void* const* d_in, const int* in_sizes, int n_in,
                              void* d_out, int out_size)
{
    const float* hidden = (const float*)d_in[0];
    // d_in[1] = attention_mask (exactly causal; implemented analytically)
    const float* Wqkv = (const float*)d_in[2];
    const float* Wo   = (const float*)d_in[3];
    float* out = (float*)d_out;

    float *qkv_ptr, *att_ptr;
    cudaGetSymbolAddress((void**)&qkv_ptr, g_qkv);
    cudaGetSymbolAddress((void**)&att_ptr, g_att);

    rope_tables_kernel<<<(S_LEN * 32 + 255) / 256, 256>>>();

    dim3 g1(3 * HID / BN, ROWS / BM);   // (24, 32)
    sgemm_kernel<<<g1, 256>>>(hidden, Wqkv, qkv_ptr, ROWS, 3 * HID, HID);

    rope_apply_kernel<<<(ROWS * 1024) / 256, 256>>>();

    const int SMEM = 16768 * 4;
    cudaFuncSetAttribute(attn_kernel, cudaFuncAttributeMaxDynamicSharedMemorySize, SMEM);
    dim3 g2(S_LEN / 64, BATCH * NH);    // (32, 32)
    attn_kernel<<<g2, 256, SMEM>>>(qkv_ptr, att_ptr);

    dim3 g3(HID / BN, ROWS / BM);       // (8, 32)
    sgemm_kernel<<<g3, 256>>>(att_ptr, Wo, out, ROWS, HID, HID);
}